// round 15
// baseline (speedup 1.0000x reference)
#include <cuda_runtime.h>
#include <cuda_bf16.h>
#include <math.h>

// ---------------- constants ----------------
#define TOPK        1000
#define CAND_CAP    2048
#define HB          65536
#define NMS_T       0.6f
#define CONF_T      0.05f
#define CTR_CLAMP_F 32.0f
#define STRIDE_F    32.0f
#define SCALE_CLAMP_F 4.1351666f   // log(1000/16) fp32

#define ROWS_PER_BLK 114           // ceil(50000/114)=439 blocks ~ 3/SM balanced
#define PACK_STRIDE  21
#define NTHR   256
#define TAILBLK 128
#define NSLOT  6
#define BARW   32
#define SRAW_B 21504               // phase-aliased smem (max of all phase needs)

struct __align__(128) PadCnt { unsigned int v; unsigned int pad[31]; };

// ---------------- zero-init scratch (ONE memset covers all) ----------------
struct __align__(16) ZeroBlob {
    unsigned int       hist[HB];          // fine 64K bins (ord>>16)
    unsigned int       chist[256];        // coarse bins (ord>>24)
    unsigned long long cand[CAND_CAP];
    float4             tbox[1024];
    float4             obox[1024];
    float              area[1024];
    float              tscore[1024];
    int                tlabel[1024];
    unsigned char      tvalid[1024];
    PadCnt             cnt[NSLOT][BARW];
    int                ncand;
};
__device__ ZeroBlob g_z;

// rowkey[m] = (ord << 12) | (4095 - argmax_col)   (fully overwritten each launch)
__device__ unsigned long long g_rowkey[1 << 17];
__device__ unsigned long long g_maskT[16 * 1024];

__device__ __forceinline__ unsigned int f2ord(float f) {
    unsigned int u = __float_as_uint(f);
    return (u & 0x80000000u) ? ~u : (u | 0x80000000u);
}
__device__ __forceinline__ float ord2f(unsigned int o) {
    unsigned int u = (o & 0x80000000u) ? (o & 0x7FFFFFFFu) : ~o;
    return __uint_as_float(u);
}
__device__ __forceinline__ unsigned long long umax64(unsigned long long a, unsigned long long b) {
    return a > b ? a : b;
}

__device__ __forceinline__ void bar_arrive(int s) {
    __syncthreads();
    if (threadIdx.x == 0) {
        __threadfence();
        atomicAdd(&g_z.cnt[s][blockIdx.x & (BARW - 1)].v, 1u);
    }
}
__device__ __forceinline__ void bar_wait(int s, unsigned int expected) {
    if (threadIdx.x < 32) {
        for (;;) {
            unsigned int v = *(volatile unsigned int*)&g_z.cnt[s][threadIdx.x].v;
            unsigned int sum = __reduce_add_sync(0xffffffffu, v);
            if (sum >= expected) break;
            __nanosleep(32);
        }
        __threadfence();
    }
    __syncthreads();
}

// =====================================================================
__global__ __launch_bounds__(NTHR, 6) void yolof_all(
    const float* __restrict__ cls, const float* __restrict__ reg,
    const float* __restrict__ anchor_size,
    const int* __restrict__ pH, const int* __restrict__ pW,
    int h_fb, int w_fb, int A, int M, int C, int nchunks,
    float* __restrict__ out)
{
    __shared__ __align__(16) char s_raw[SRAW_B];
    __shared__ unsigned int s_chist[256];
    __shared__ unsigned long long s_validw[16], s_rem[16], s_keep[16];
    __shared__ int s_ck, s_above, s_B;
    __shared__ int s_cnt, s_base;

    const int bid  = blockIdx.x;
    const int tid  = threadIdx.x;
    const int lane = tid & 31;
    const int wid  = tid >> 5;
    const unsigned int NB = gridDim.x;

    if (tid < 256) s_chist[tid] = 0;
    __syncthreads();

    // ---------------- P1: scores (packed-key streamer, 114 rows/block) ----------------
    if (C == 80) {
        unsigned long long* sp = (unsigned long long*)s_raw;
        int base_row = bid * ROWS_PER_BLK;
        if (base_row < M) {
            int nrows = M - base_row;
            if (nrows > ROWS_PER_BLK) nrows = ROWS_PER_BLK;
            const float4* src = (const float4*)(cls + (size_t)base_row * 80);
            int nf4 = nrows * 20;
            #pragma unroll
            for (int q = 0; q < 9; q++) {
                int i = tid + q * NTHR;
                if (i < nf4) {
                    float4 v = src[i];                     // 9 independent LDG.128
                    int g4 = i * 4;
                    int r = g4 / 80;
                    int cb = g4 - r * 80;
                    unsigned long long k0 = ((unsigned long long)f2ord(v.x) << 12) | (unsigned)(4095 - cb);
                    unsigned long long k1 = ((unsigned long long)f2ord(v.y) << 12) | (unsigned)(4094 - cb);
                    unsigned long long k2 = ((unsigned long long)f2ord(v.z) << 12) | (unsigned)(4093 - cb);
                    unsigned long long k3 = ((unsigned long long)f2ord(v.w) << 12) | (unsigned)(4092 - cb);
                    sp[r * PACK_STRIDE + (cb >> 2)] = umax64(umax64(k0, k1), umax64(k2, k3));
                }
            }
            __syncthreads();
            if (tid < nrows) {
                const unsigned long long* rp = &sp[tid * PACK_STRIDE];
                unsigned long long best = rp[0];
                #pragma unroll
                for (int j = 1; j < 20; j++) best = umax64(best, rp[j]);
                int row = base_row + tid;
                g_rowkey[row] = best;
                unsigned int ord = (unsigned int)(best >> 12);
                atomicAdd(&g_z.hist[ord >> 16], 1u);
                atomicAdd(&s_chist[ord >> 24], 1u);
            }
        }
    } else {
        int gw = (bid * NTHR + tid) >> 5, NW = (NB * NTHR) >> 5;
        for (int r = gw; r < M; r += NW) {
            const float* row = cls + (size_t)r * C;
            float v = -INFINITY; int bi = 0;
            for (int c = lane; c < C; c += 32) {
                float x = row[c];
                if (x > v) { v = x; bi = c; }
            }
            #pragma unroll
            for (int off = 16; off > 0; off >>= 1) {
                float ov = __shfl_down_sync(0xffffffffu, v, off);
                int   ob = __shfl_down_sync(0xffffffffu, bi, off);
                if (ov > v || (ov == v && ob < bi)) { v = ov; bi = ob; }
            }
            if (lane == 0) {
                unsigned int o = f2ord(v);
                int ci = bi < 4095 ? bi : 4095;
                g_rowkey[r] = ((unsigned long long)o << 12) | (unsigned)(4095 - ci);
                atomicAdd(&g_z.hist[o >> 16], 1u);
                atomicAdd(&s_chist[o >> 24], 1u);
            }
        }
    }
    __syncthreads();
    if (tid < 256) {
        unsigned int v = s_chist[tid];
        if (v) atomicAdd(&g_z.chist[tid], v);
    }
    bar_arrive(0);
    if (bid >= TAILBLK) return;
    bar_wait(0, NB);

    // ---------------- P2': per-block threshold (redundant, no barrier) ----------------
    {
        int* cs = (int*)s_raw;
        cs[tid] = (tid < 256) ? (int)g_z.chist[tid] : 0;
        __syncthreads();
        for (int off = 1; off < 256; off <<= 1) {
            int add = (tid < 256 && tid + off < 256) ? cs[tid + off] : 0;
            __syncthreads();
            if (tid < 256) cs[tid] += add;
            __syncthreads();
        }
        if (tid == 0) { s_ck = -1; s_B = 0; }
        __syncthreads();
        if (tid < 256) {
            int Sm = cs[tid];
            int Sn = (tid < 255) ? cs[tid + 1] : 0;
            if (Sm >= TOPK && Sn < TOPK) { s_ck = tid; s_above = Sn; }
        }
        __syncthreads();
        int ck = s_ck;
        if (ck >= 0) {
            cs[tid] = (tid < 256) ? (int)g_z.hist[ck * 256 + tid] : 0;
            __syncthreads();
            for (int off = 1; off < 256; off <<= 1) {
                int add = (tid < 256 && tid + off < 256) ? cs[tid + off] : 0;
                __syncthreads();
                if (tid < 256) cs[tid] += add;
                __syncthreads();
            }
            if (tid < 256) {
                int above = s_above;
                int Hm = cs[tid] + above;
                int Hn = ((tid < 255) ? cs[tid + 1] : 0) + above;
                if (Hm >= TOPK && Hn < TOPK) s_B = ck * 256 + tid;
            }
        }
        __syncthreads();
    }

    // ---------------- P3: compact (two-level; ONE global atomic per block) ----------------
    {
        int B = s_B;
        unsigned long long* list = (unsigned long long*)s_raw;   // block-local cand keys
        if (tid == 0) s_cnt = 0;
        __syncthreads();
        // thread gid covers rows {2*gid, 2*gid+1}; block covers 512 contiguous rows
        int gid = bid * NTHR + tid;
        int p = gid;                       // pair index
        if (2 * p < M) {
            ulonglong2 rk = ((const ulonglong2*)g_rowkey)[p];
            #pragma unroll
            for (int h = 0; h < 2; h++) {
                int m = 2 * p + h;
                if (m < M) {
                    unsigned long long key = h ? rk.y : rk.x;
                    unsigned int o = (unsigned int)(key >> 12);
                    if ((int)(o >> 16) >= B) {
                        int idx = atomicAdd(&s_cnt, 1);
                        if (idx < 2048)
                            list[idx] = ((unsigned long long)o << 20) |
                                        (unsigned long long)(0xFFFFFu - (unsigned)m);
                    }
                }
            }
        }
        // remaining pairs (M > 2*TAILBLK*NTHR not possible for M<=65536; guard anyway)
        for (p = gid + TAILBLK * NTHR; 2 * p < M; p += TAILBLK * NTHR) {
            ulonglong2 rk = ((const ulonglong2*)g_rowkey)[p];
            #pragma unroll
            for (int h = 0; h < 2; h++) {
                int m = 2 * p + h;
                if (m < M) {
                    unsigned long long key = h ? rk.y : rk.x;
                    unsigned int o = (unsigned int)(key >> 12);
                    if ((int)(o >> 16) >= B) {
                        int idx = atomicAdd(&s_cnt, 1);
                        if (idx < 2048)
                            list[idx] = ((unsigned long long)o << 20) |
                                        (unsigned long long)(0xFFFFFu - (unsigned)m);
                    }
                }
            }
        }
        __syncthreads();
        int cnt = s_cnt; if (cnt > 2048) cnt = 2048;
        if (tid == 0 && cnt > 0) s_base = atomicAdd(&g_z.ncand, cnt);
        __syncthreads();
        if (cnt > 0) {
            int base = s_base;
            for (int i = tid; i < cnt; i += NTHR) {
                int pdst = base + i;
                if (pdst < CAND_CAP) g_z.cand[pdst] = list[i];
            }
        }
    }
    bar_arrive(1); bar_wait(1, TAILBLK);

    // ---------------- P4: rank-select + decode (ALL 128 tail blocks) ----------------
    {
        unsigned long long* sk = (unsigned long long*)s_raw;
        __syncthreads();
        for (int v = tid; v < CAND_CAP; v += NTHR) sk[v] = g_z.cand[v];
        __syncthreads();
        int cand = bid * 16 + (tid >> 4);
        int part = tid & 15;
        unsigned long long my = sk[cand];
        int rank = 0;
        #pragma unroll 8
        for (int k = 0; k < 128; k++) rank += (sk[part + 16 * k] > my) ? 1 : 0;
        rank += __shfl_down_sync(0xffffffffu, rank, 8, 16);
        rank += __shfl_down_sync(0xffffffffu, rank, 4, 16);
        rank += __shfl_down_sync(0xffffffffu, rank, 2, 16);
        rank += __shfl_down_sync(0xffffffffu, rank, 1, 16);

        if (part == 0 && my != 0ULL && rank < TOPK) {
            int m = (int)(0xFFFFFu - (unsigned)(my & 0xFFFFFu));
            unsigned int o = (unsigned int)(my >> 20);
            float logit = ord2f(o);
            float score = 1.0f / (1.0f + expf(-logit));
            int label = 4095 - (int)(g_rowkey[m] & 0xFFFULL);
            const float4 r4 = ((const float4*)reg)[m];
            int a    = m % A;
            int cell = m / A;
            int w = pW ? *pW : w_fb;
            int x = cell % w, y = cell / w;
            float ax = ((float)x + 0.5f) * STRIDE_F;
            float ay = ((float)y + 0.5f) * STRIDE_F;
            float aw = anchor_size[a * 2 + 0];
            float ah = anchor_size[a * 2 + 1];
            float offx = fminf(fmaxf(r4.x * aw, -CTR_CLAMP_F), CTR_CLAMP_F);
            float offy = fminf(fmaxf(r4.y * ah, -CTR_CLAMP_F), CTR_CLAMP_F);
            float cx = ax + offx, cy = ay + offy;
            float bw = aw * expf(fminf(r4.z, SCALE_CLAMP_F));
            float bh = ah * expf(fminf(r4.w, SCALE_CLAMP_F));
            float4 box = make_float4(cx - 0.5f * bw, cy - 0.5f * bh,
                                     cx + 0.5f * bw, cy + 0.5f * bh);
            float offc = (float)label * 100000.0f;
            float4 ob = make_float4(box.x + offc, box.y + offc,
                                    box.z + offc, box.w + offc);
            g_z.tbox[rank]   = box;
            g_z.obox[rank]   = ob;
            g_z.area[rank]   = (ob.z - ob.x) * (ob.w - ob.y);
            g_z.tscore[rank] = score;
            g_z.tlabel[rank] = label;
            g_z.tvalid[rank] = (score >= CONF_T) ? 1 : 0;
        }
    }
    bar_arrive(2); bar_wait(2, TAILBLK);

    // ---------------- P5: suppression mask (smem-staged boxes) ----------------
    {
        float4* s_ob = (float4*)s_raw;                 // 16KB
        float*  s_ar = (float*)(s_raw + 16384);        // 4KB
        __syncthreads();
        for (int i = tid; i < 1024; i += NTHR) {
            s_ob[i] = g_z.obox[i];
            s_ar[i] = g_z.area[i];
        }
        __syncthreads();
        int nt = TAILBLK * NTHR;
        for (int u = bid * NTHR + tid; u < 16 * 1024; u += nt) {
            int w = u >> 10;
            int i = u & 1023;
            if (i >= TOPK) continue;
            float4 bi4 = s_ob[i];
            float ai = s_ar[i];
            unsigned long long bits = 0ULL;
            int jbase = w * 64;
            if (jbase + 63 > i) {
                #pragma unroll 4
                for (int b = 0; b < 64; b++) {
                    int j = jbase + b;
                    if (j > i && j < TOPK) {
                        float4 bj = s_ob[j];
                        float xx1 = fmaxf(bi4.x, bj.x);
                        float yy1 = fmaxf(bi4.y, bj.y);
                        float xx2 = fminf(bi4.z, bj.z);
                        float yy2 = fminf(bi4.w, bj.w);
                        float inter = fmaxf(1e-28f, xx2 - xx1) * fmaxf(1e-28f, yy2 - yy1);
                        float iou = inter / (ai + s_ar[j] - inter + 1e-14f);
                        if (iou > NMS_T) bits |= (1ULL << b);
                    }
                }
            }
            g_maskT[w * 1024 + i] = bits;
        }
    }
    bar_arrive(3);
    if (bid != 0) return;
    bar_wait(3, TAILBLK);

    // ---------------- P6: greedy NMS + outputs (block 0) ----------------
    __syncthreads();
    unsigned long long* diag = (unsigned long long*)s_raw;
    for (int i = tid; i < TOPK; i += NTHR)
        diag[i] = g_maskT[(i >> 6) * 1024 + i];
    if (tid < 16) {
        unsigned long long vw = 0ULL;
        #pragma unroll 4
        for (int k = 0; k < 64; k++) {
            int i = tid * 64 + k;
            if (i < TOPK && g_z.tvalid[i]) vw |= (1ULL << k);
        }
        s_validw[tid] = vw;
        s_rem[tid] = 0ULL;
        s_keep[tid] = 0ULL;
    }
    __syncthreads();

    for (int c = 0; c < 16; c++) {
        int wA = 2 * wid + 1, wB = 2 * wid + 2;
        unsigned long long a0 = 0, a1 = 0, b0 = 0, b1 = 0;
        int r0 = c * 64 + 2 * lane;
        if (wA > c && wA < 16) {
            a0 = g_maskT[wA * 1024 + r0];
            a1 = g_maskT[wA * 1024 + r0 + 1];
        }
        if (wB > c && wB < 16) {
            b0 = g_maskT[wB * 1024 + r0];
            b1 = g_maskT[wB * 1024 + r0 + 1];
        }
        if (wid == 0) {
            unsigned long long alive = s_validw[c] & ~s_rem[c];
            unsigned long long dd =
                (((alive >> (2 * lane)) & 1ULL) ? diag[c * 64 + 2 * lane] : 0ULL) |
                (((alive >> (2 * lane + 1)) & 1ULL) ? diag[c * 64 + 2 * lane + 1] : 0ULL);
            #pragma unroll
            for (int off = 16; off > 0; off >>= 1)
                dd |= __shfl_down_sync(0xffffffffu, dd, off);
            if (lane == 0) {
                unsigned long long keepw;
                if ((dd & alive) == 0ULL) {
                    keepw = alive;
                } else {
                    keepw = 0ULL;
                    while (alive) {
                        int b = __ffsll((long long)alive) - 1;
                        keepw |= (1ULL << b);
                        unsigned long long d = diag[c * 64 + b];
                        alive &= ~(d | (1ULL << b));
                    }
                }
                s_keep[c] = keepw;
            }
        }
        __syncthreads();
        unsigned long long kw = s_keep[c];
        if (wA > c && wA < 16) {
            unsigned long long acc =
                (((kw >> (2 * lane)) & 1ULL) ? a0 : 0ULL) |
                (((kw >> (2 * lane + 1)) & 1ULL) ? a1 : 0ULL);
            #pragma unroll
            for (int off = 16; off > 0; off >>= 1)
                acc |= __shfl_down_sync(0xffffffffu, acc, off);
            if (lane == 0) s_rem[wA] |= acc;
        }
        if (wB > c && wB < 16) {
            unsigned long long acc =
                (((kw >> (2 * lane)) & 1ULL) ? b0 : 0ULL) |
                (((kw >> (2 * lane + 1)) & 1ULL) ? b1 : 0ULL);
            #pragma unroll
            for (int off = 16; off > 0; off >>= 1)
                acc |= __shfl_down_sync(0xffffffffu, acc, off);
            if (lane == 0) s_rem[wB] |= acc;
        }
        __syncthreads();
    }

    {
        int W = pW ? *pW : w_fb;
        int H = pH ? *pH : h_fb;
        float img_w = (float)W * STRIDE_F;
        float img_h = (float)H * STRIDE_F;
        for (int i = tid; i < TOPK; i += NTHR) {
            bool keep = (s_keep[i >> 6] >> (i & 63)) & 1ULL;
            float kf = keep ? 1.0f : 0.0f;
            float4 b = g_z.tbox[i];
            out[i * 4 + 0] = fminf(fmaxf(b.x / img_w, 0.f), 1.f) * kf;
            out[i * 4 + 1] = fminf(fmaxf(b.y / img_h, 0.f), 1.f) * kf;
            out[i * 4 + 2] = fminf(fmaxf(b.z / img_w, 0.f), 1.f) * kf;
            out[i * 4 + 3] = fminf(fmaxf(b.w / img_h, 0.f), 1.f) * kf;
            out[4 * TOPK + i] = g_z.tscore[i] * kf;
            out[5 * TOPK + i] = keep ? (float)g_z.tlabel[i] : -1.0f;
            out[6 * TOPK + i] = kf;
        }
    }
}

// ---------------- launch ----------------
extern "C" void kernel_launch(void* const* d_in, const int* in_sizes, int n_in,
                              void* d_out, int out_size) {
    const float* cls  = (const float*)d_in[0];
    const float* reg  = (const float*)d_in[1];
    const float* anch = (const float*)d_in[2];
    const int* pH = (n_in > 3) ? (const int*)d_in[3] : nullptr;
    const int* pW = (n_in > 4) ? (const int*)d_in[4] : nullptr;

    int M = in_sizes[1] / 4;
    int C = in_sizes[0] / M;
    int A = in_sizes[2] / 2;

    int cells = M / A;
    int w_guess = 1;
    while ((w_guess + 1) * (w_guess + 1) <= cells) w_guess++;
    int h_guess = cells / w_guess;

    int nchunks = (M + ROWS_PER_BLK - 1) / ROWS_PER_BLK;
    int grid = nchunks;
    if (grid > 888) grid = 888;
    if (grid < TAILBLK) grid = TAILBLK;

    void* zp = nullptr;
    cudaGetSymbolAddress(&zp, g_z);
    cudaMemsetAsync(zp, 0, sizeof(ZeroBlob));

    yolof_all<<<grid, NTHR>>>(cls, reg, anch, pH, pW,
                              h_guess, w_guess, A, M, C, nchunks, (float*)d_out);
}

// round 16
// speedup vs baseline: 1.0019x; 1.0019x over previous
#include <cuda_runtime.h>
#include <cuda_bf16.h>
#include <math.h>

// ---------------- constants ----------------
#define TOPK        1000
#define CAND_CAP    2048
#define HB          65536
#define NMS_T       0.6f
#define CONF_T      0.05f
#define CTR_CLAMP_F 32.0f
#define STRIDE_F    32.0f
#define SCALE_CLAMP_F 4.1351666f   // log(1000/16) fp32

#define ROWS_PER_BLK 114
#define PACK_STRIDE  21
#define NTHR   256
#define TAILBLK 128
#define NSLOT  4
#define BARW   32
#define SRAW_B 21504

struct __align__(128) PadCnt { unsigned int v; unsigned int pad[31]; };

// ---------------- zero-init scratch (ONE memset covers all) ----------------
struct __align__(16) ZeroBlob {
    unsigned int       hist[HB];          // fine 64K bins (ord>>16)
    unsigned int       chist[256];        // coarse bins (ord>>24)
    unsigned long long cand[CAND_CAP];
    float4             tbox[1024];
    float4             obox[1024];
    float              area[1024];
    float              tscore[1024];
    int                tlabel[1024];
    unsigned char      tvalid[1024];
    PadCnt             cnt[NSLOT][BARW];
    int                ncand;
};
__device__ ZeroBlob g_z;

// rowkey[m] = (ord << 12) | (4095 - argmax_col)
__device__ unsigned long long g_rowkey[1 << 17];
__device__ unsigned long long g_maskT[16 * 1024];

__device__ __forceinline__ unsigned int f2ord(float f) {
    unsigned int u = __float_as_uint(f);
    return (u & 0x80000000u) ? ~u : (u | 0x80000000u);
}
__device__ __forceinline__ float ord2f(unsigned int o) {
    unsigned int u = (o & 0x80000000u) ? (o & 0x7FFFFFFFu) : ~o;
    return __uint_as_float(u);
}
__device__ __forceinline__ unsigned long long umax64(unsigned long long a, unsigned long long b) {
    return a > b ? a : b;
}

__device__ __forceinline__ void bar_arrive(int s) {
    __syncthreads();
    if (threadIdx.x == 0) {
        __threadfence();
        atomicAdd(&g_z.cnt[s][blockIdx.x & (BARW - 1)].v, 1u);
    }
}
__device__ __forceinline__ void bar_wait(int s, unsigned int expected) {
    if (threadIdx.x < 32) {
        for (;;) {
            unsigned int v = *(volatile unsigned int*)&g_z.cnt[s][threadIdx.x].v;
            unsigned int sum = __reduce_add_sync(0xffffffffu, v);
            if (sum >= expected) break;
            __nanosleep(32);
        }
        __threadfence();
    }
    __syncthreads();
}

// =====================================================================
// Kernel 1: P1 scores (packed-key streamer) — no grid barrier
// =====================================================================
__global__ __launch_bounds__(NTHR, 6) void k_p1(
    const float* __restrict__ cls, int M, int C)
{
    __shared__ __align__(16) char s_raw[SRAW_B];
    __shared__ unsigned int s_chist[256];

    const int bid  = blockIdx.x;
    const int tid  = threadIdx.x;
    const int lane = tid & 31;
    const unsigned int NB = gridDim.x;

    if (tid < 256) s_chist[tid] = 0;
    __syncthreads();

    if (C == 80) {
        unsigned long long* sp = (unsigned long long*)s_raw;
        int base_row = bid * ROWS_PER_BLK;
        if (base_row < M) {
            int nrows = M - base_row;
            if (nrows > ROWS_PER_BLK) nrows = ROWS_PER_BLK;
            const float4* src = (const float4*)(cls + (size_t)base_row * 80);
            int nf4 = nrows * 20;
            #pragma unroll
            for (int q = 0; q < 9; q++) {
                int i = tid + q * NTHR;
                if (i < nf4) {
                    float4 v = src[i];
                    int g4 = i * 4;
                    int r = g4 / 80;
                    int cb = g4 - r * 80;
                    unsigned long long k0 = ((unsigned long long)f2ord(v.x) << 12) | (unsigned)(4095 - cb);
                    unsigned long long k1 = ((unsigned long long)f2ord(v.y) << 12) | (unsigned)(4094 - cb);
                    unsigned long long k2 = ((unsigned long long)f2ord(v.z) << 12) | (unsigned)(4093 - cb);
                    unsigned long long k3 = ((unsigned long long)f2ord(v.w) << 12) | (unsigned)(4092 - cb);
                    sp[r * PACK_STRIDE + (cb >> 2)] = umax64(umax64(k0, k1), umax64(k2, k3));
                }
            }
            __syncthreads();
            if (tid < nrows) {
                const unsigned long long* rp = &sp[tid * PACK_STRIDE];
                unsigned long long best = rp[0];
                #pragma unroll
                for (int j = 1; j < 20; j++) best = umax64(best, rp[j]);
                int row = base_row + tid;
                g_rowkey[row] = best;
                unsigned int ord = (unsigned int)(best >> 12);
                atomicAdd(&g_z.hist[ord >> 16], 1u);
                atomicAdd(&s_chist[ord >> 24], 1u);
            }
        }
    } else {
        int gw = (bid * NTHR + tid) >> 5, NW = (NB * NTHR) >> 5;
        for (int r = gw; r < M; r += NW) {
            const float* row = cls + (size_t)r * C;
            float v = -INFINITY; int bi = 0;
            for (int c = lane; c < C; c += 32) {
                float x = row[c];
                if (x > v) { v = x; bi = c; }
            }
            #pragma unroll
            for (int off = 16; off > 0; off >>= 1) {
                float ov = __shfl_down_sync(0xffffffffu, v, off);
                int   ob = __shfl_down_sync(0xffffffffu, bi, off);
                if (ov > v || (ov == v && ob < bi)) { v = ov; bi = ob; }
            }
            if (lane == 0) {
                unsigned int o = f2ord(v);
                int ci = bi < 4095 ? bi : 4095;
                g_rowkey[r] = ((unsigned long long)o << 12) | (unsigned)(4095 - ci);
                atomicAdd(&g_z.hist[o >> 16], 1u);
                atomicAdd(&s_chist[o >> 24], 1u);
            }
        }
    }
    __syncthreads();
    if (tid < 256) {
        unsigned int v = s_chist[tid];
        if (v) atomicAdd(&g_z.chist[tid], v);
    }
}

// =====================================================================
// Kernel 2: tail (threshold/compact/rank/mask/NMS/output) — 128 blocks
// =====================================================================
__global__ __launch_bounds__(NTHR, 6) void k_tail(
    const float* __restrict__ reg, const float* __restrict__ anchor_size,
    const int* __restrict__ pH, const int* __restrict__ pW,
    int h_fb, int w_fb, int A, int M,
    float* __restrict__ out)
{
    __shared__ __align__(16) char s_raw[SRAW_B];
    __shared__ unsigned long long s_validw[16], s_rem[16], s_keep[16];
    __shared__ int s_ck, s_above, s_B;
    __shared__ int s_cnt, s_base;

    const int bid  = blockIdx.x;
    const int tid  = threadIdx.x;
    const int lane = tid & 31;
    const int wid  = tid >> 5;

    // ---------------- P2': per-block threshold ----------------
    {
        int* cs = (int*)s_raw;
        cs[tid] = (tid < 256) ? (int)g_z.chist[tid] : 0;
        __syncthreads();
        for (int off = 1; off < 256; off <<= 1) {
            int add = (tid < 256 && tid + off < 256) ? cs[tid + off] : 0;
            __syncthreads();
            if (tid < 256) cs[tid] += add;
            __syncthreads();
        }
        if (tid == 0) { s_ck = -1; s_B = 0; }
        __syncthreads();
        if (tid < 256) {
            int Sm = cs[tid];
            int Sn = (tid < 255) ? cs[tid + 1] : 0;
            if (Sm >= TOPK && Sn < TOPK) { s_ck = tid; s_above = Sn; }
        }
        __syncthreads();
        int ck = s_ck;
        if (ck >= 0) {
            cs[tid] = (tid < 256) ? (int)g_z.hist[ck * 256 + tid] : 0;
            __syncthreads();
            for (int off = 1; off < 256; off <<= 1) {
                int add = (tid < 256 && tid + off < 256) ? cs[tid + off] : 0;
                __syncthreads();
                if (tid < 256) cs[tid] += add;
                __syncthreads();
            }
            if (tid < 256) {
                int above = s_above;
                int Hm = cs[tid] + above;
                int Hn = ((tid < 255) ? cs[tid + 1] : 0) + above;
                if (Hm >= TOPK && Hn < TOPK) s_B = ck * 256 + tid;
            }
        }
        __syncthreads();
    }

    // ---------------- P3: compact (two-level) ----------------
    {
        int B = s_B;
        unsigned long long* list = (unsigned long long*)s_raw;
        if (tid == 0) s_cnt = 0;
        __syncthreads();
        int gid = bid * NTHR + tid;
        for (int p = gid; 2 * p < M; p += TAILBLK * NTHR) {
            ulonglong2 rk = ((const ulonglong2*)g_rowkey)[p];
            #pragma unroll
            for (int h = 0; h < 2; h++) {
                int m = 2 * p + h;
                if (m < M) {
                    unsigned long long key = h ? rk.y : rk.x;
                    unsigned int o = (unsigned int)(key >> 12);
                    if ((int)(o >> 16) >= B) {
                        int idx = atomicAdd(&s_cnt, 1);
                        if (idx < 2048)
                            list[idx] = ((unsigned long long)o << 20) |
                                        (unsigned long long)(0xFFFFFu - (unsigned)m);
                    }
                }
            }
        }
        __syncthreads();
        int cnt = s_cnt; if (cnt > 2048) cnt = 2048;
        if (tid == 0 && cnt > 0) s_base = atomicAdd(&g_z.ncand, cnt);
        __syncthreads();
        if (cnt > 0) {
            int base = s_base;
            for (int i = tid; i < cnt; i += NTHR) {
                int pdst = base + i;
                if (pdst < CAND_CAP) g_z.cand[pdst] = list[i];
            }
        }
    }
    bar_arrive(0); bar_wait(0, TAILBLK);

    // ---------------- P4: rank-select + decode ----------------
    {
        unsigned long long* sk = (unsigned long long*)s_raw;
        __syncthreads();
        for (int v = tid; v < CAND_CAP; v += NTHR) sk[v] = g_z.cand[v];
        __syncthreads();
        int cand = bid * 16 + (tid >> 4);
        int part = tid & 15;
        unsigned long long my = sk[cand];
        int rank = 0;
        #pragma unroll 8
        for (int k = 0; k < 128; k++) rank += (sk[part + 16 * k] > my) ? 1 : 0;
        rank += __shfl_down_sync(0xffffffffu, rank, 8, 16);
        rank += __shfl_down_sync(0xffffffffu, rank, 4, 16);
        rank += __shfl_down_sync(0xffffffffu, rank, 2, 16);
        rank += __shfl_down_sync(0xffffffffu, rank, 1, 16);

        if (part == 0 && my != 0ULL && rank < TOPK) {
            int m = (int)(0xFFFFFu - (unsigned)(my & 0xFFFFFu));
            unsigned int o = (unsigned int)(my >> 20);
            float logit = ord2f(o);
            float score = 1.0f / (1.0f + expf(-logit));
            int label = 4095 - (int)(g_rowkey[m] & 0xFFFULL);
            const float4 r4 = ((const float4*)reg)[m];
            int a    = m % A;
            int cell = m / A;
            int w = pW ? *pW : w_fb;
            int x = cell % w, y = cell / w;
            float ax = ((float)x + 0.5f) * STRIDE_F;
            float ay = ((float)y + 0.5f) * STRIDE_F;
            float aw = anchor_size[a * 2 + 0];
            float ah = anchor_size[a * 2 + 1];
            float offx = fminf(fmaxf(r4.x * aw, -CTR_CLAMP_F), CTR_CLAMP_F);
            float offy = fminf(fmaxf(r4.y * ah, -CTR_CLAMP_F), CTR_CLAMP_F);
            float cx = ax + offx, cy = ay + offy;
            float bw = aw * expf(fminf(r4.z, SCALE_CLAMP_F));
            float bh = ah * expf(fminf(r4.w, SCALE_CLAMP_F));
            float4 box = make_float4(cx - 0.5f * bw, cy - 0.5f * bh,
                                     cx + 0.5f * bw, cy + 0.5f * bh);
            float offc = (float)label * 100000.0f;
            float4 ob = make_float4(box.x + offc, box.y + offc,
                                    box.z + offc, box.w + offc);
            g_z.tbox[rank]   = box;
            g_z.obox[rank]   = ob;
            g_z.area[rank]   = (ob.z - ob.x) * (ob.w - ob.y);
            g_z.tscore[rank] = score;
            g_z.tlabel[rank] = label;
            g_z.tvalid[rank] = (score >= CONF_T) ? 1 : 0;
        }
    }
    bar_arrive(1); bar_wait(1, TAILBLK);

    // ---------------- P5: suppression mask (smem-staged boxes) ----------------
    {
        float4* s_ob = (float4*)s_raw;
        float*  s_ar = (float*)(s_raw + 16384);
        __syncthreads();
        for (int i = tid; i < 1024; i += NTHR) {
            s_ob[i] = g_z.obox[i];
            s_ar[i] = g_z.area[i];
        }
        __syncthreads();
        int nt = TAILBLK * NTHR;
        for (int u = bid * NTHR + tid; u < 16 * 1024; u += nt) {
            int w = u >> 10;
            int i = u & 1023;
            if (i >= TOPK) continue;
            float4 bi4 = s_ob[i];
            float ai = s_ar[i];
            unsigned long long bits = 0ULL;
            int jbase = w * 64;
            if (jbase + 63 > i) {
                #pragma unroll 4
                for (int b = 0; b < 64; b++) {
                    int j = jbase + b;
                    if (j > i && j < TOPK) {
                        float4 bj = s_ob[j];
                        float xx1 = fmaxf(bi4.x, bj.x);
                        float yy1 = fmaxf(bi4.y, bj.y);
                        float xx2 = fminf(bi4.z, bj.z);
                        float yy2 = fminf(bi4.w, bj.w);
                        float inter = fmaxf(1e-28f, xx2 - xx1) * fmaxf(1e-28f, yy2 - yy1);
                        float iou = inter / (ai + s_ar[j] - inter + 1e-14f);
                        if (iou > NMS_T) bits |= (1ULL << b);
                    }
                }
            }
            g_maskT[w * 1024 + i] = bits;
        }
    }
    bar_arrive(2);
    if (bid != 0) return;
    bar_wait(2, TAILBLK);

    // ---------------- P6: greedy NMS + outputs (block 0) ----------------
    __syncthreads();
    unsigned long long* diag = (unsigned long long*)s_raw;
    for (int i = tid; i < TOPK; i += NTHR)
        diag[i] = g_maskT[(i >> 6) * 1024 + i];
    if (tid < 16) {
        unsigned long long vw = 0ULL;
        #pragma unroll 4
        for (int k = 0; k < 64; k++) {
            int i = tid * 64 + k;
            if (i < TOPK && g_z.tvalid[i]) vw |= (1ULL << k);
        }
        s_validw[tid] = vw;
        s_rem[tid] = 0ULL;
        s_keep[tid] = 0ULL;
    }
    __syncthreads();

    for (int c = 0; c < 16; c++) {
        int wA = 2 * wid + 1, wB = 2 * wid + 2;
        unsigned long long a0 = 0, a1 = 0, b0 = 0, b1 = 0;
        int r0 = c * 64 + 2 * lane;
        if (wA > c && wA < 16) {
            a0 = g_maskT[wA * 1024 + r0];
            a1 = g_maskT[wA * 1024 + r0 + 1];
        }
        if (wB > c && wB < 16) {
            b0 = g_maskT[wB * 1024 + r0];
            b1 = g_maskT[wB * 1024 + r0 + 1];
        }
        if (wid == 0) {
            unsigned long long alive = s_validw[c] & ~s_rem[c];
            unsigned long long dd =
                (((alive >> (2 * lane)) & 1ULL) ? diag[c * 64 + 2 * lane] : 0ULL) |
                (((alive >> (2 * lane + 1)) & 1ULL) ? diag[c * 64 + 2 * lane + 1] : 0ULL);
            #pragma unroll
            for (int off = 16; off > 0; off >>= 1)
                dd |= __shfl_down_sync(0xffffffffu, dd, off);
            if (lane == 0) {
                unsigned long long keepw;
                if ((dd & alive) == 0ULL) {
                    keepw = alive;
                } else {
                    keepw = 0ULL;
                    while (alive) {
                        int b = __ffsll((long long)alive) - 1;
                        keepw |= (1ULL << b);
                        unsigned long long d = diag[c * 64 + b];
                        alive &= ~(d | (1ULL << b));
                    }
                }
                s_keep[c] = keepw;
            }
        }
        __syncthreads();
        unsigned long long kw = s_keep[c];
        if (wA > c && wA < 16) {
            unsigned long long acc =
                (((kw >> (2 * lane)) & 1ULL) ? a0 : 0ULL) |
                (((kw >> (2 * lane + 1)) & 1ULL) ? a1 : 0ULL);
            #pragma unroll
            for (int off = 16; off > 0; off >>= 1)
                acc |= __shfl_down_sync(0xffffffffu, acc, off);
            if (lane == 0) s_rem[wA] |= acc;
        }
        if (wB > c && wB < 16) {
            unsigned long long acc =
                (((kw >> (2 * lane)) & 1ULL) ? b0 : 0ULL) |
                (((kw >> (2 * lane + 1)) & 1ULL) ? b1 : 0ULL);
            #pragma unroll
            for (int off = 16; off > 0; off >>= 1)
                acc |= __shfl_down_sync(0xffffffffu, acc, off);
            if (lane == 0) s_rem[wB] |= acc;
        }
        __syncthreads();
    }

    {
        int W = pW ? *pW : w_fb;
        int H = pH ? *pH : h_fb;
        float img_w = (float)W * STRIDE_F;
        float img_h = (float)H * STRIDE_F;
        for (int i = tid; i < TOPK; i += NTHR) {
            bool keep = (s_keep[i >> 6] >> (i & 63)) & 1ULL;
            float kf = keep ? 1.0f : 0.0f;
            float4 b = g_z.tbox[i];
            out[i * 4 + 0] = fminf(fmaxf(b.x / img_w, 0.f), 1.f) * kf;
            out[i * 4 + 1] = fminf(fmaxf(b.y / img_h, 0.f), 1.f) * kf;
            out[i * 4 + 2] = fminf(fmaxf(b.z / img_w, 0.f), 1.f) * kf;
            out[i * 4 + 3] = fminf(fmaxf(b.w / img_h, 0.f), 1.f) * kf;
            out[4 * TOPK + i] = g_z.tscore[i] * kf;
            out[5 * TOPK + i] = keep ? (float)g_z.tlabel[i] : -1.0f;
            out[6 * TOPK + i] = kf;
        }
    }
}

// ---------------- launch ----------------
extern "C" void kernel_launch(void* const* d_in, const int* in_sizes, int n_in,
                              void* d_out, int out_size) {
    const float* cls  = (const float*)d_in[0];
    const float* reg  = (const float*)d_in[1];
    const float* anch = (const float*)d_in[2];
    const int* pH = (n_in > 3) ? (const int*)d_in[3] : nullptr;
    const int* pW = (n_in > 4) ? (const int*)d_in[4] : nullptr;

    int M = in_sizes[1] / 4;
    int C = in_sizes[0] / M;
    int A = in_sizes[2] / 2;

    int cells = M / A;
    int w_guess = 1;
    while ((w_guess + 1) * (w_guess + 1) <= cells) w_guess++;
    int h_guess = cells / w_guess;

    int grid1 = (M + ROWS_PER_BLK - 1) / ROWS_PER_BLK;

    void* zp = nullptr;
    cudaGetSymbolAddress(&zp, g_z);
    cudaMemsetAsync(zp, 0, sizeof(ZeroBlob));

    k_p1<<<grid1, NTHR>>>(cls, M, C);
    k_tail<<<TAILBLK, NTHR>>>(reg, anch, pH, pW, h_guess, w_guess, A, M, (float*)d_out);
}